// round 1
// baseline (speedup 1.0000x reference)
#include <cuda_runtime.h>
#include <cstddef>

// Pixel_RNNcontrol: h_t = tanh(x_t @ W_ih^T + h_{t-1} @ W_hh^T + b), out = sigmoid(10 h_t)
// T=128, B=262144, I=H=2. One thread handles 2 batch elements (float4 lanes).

__device__ __forceinline__ float fast_tanh(float z) {
    // tanh(z) = (e^{2z}-1)/(e^{2z}+1); z bounded (|z| <= |x|+|h|+|b| ~ 7) -> no overflow
    float e = __expf(2.0f * z);
    return __fdividef(e - 1.0f, e + 1.0f);
}

__device__ __forceinline__ float fast_sig10(float h) {
    // sigmoid(10h), h in (-1,1)
    return __fdividef(1.0f, 1.0f + __expf(-10.0f * h));
}

__global__ void __launch_bounds__(256)
rnn_sigmoid_kernel(const float4* __restrict__ x4,
                   const float4* __restrict__ h04,
                   const float*  __restrict__ Wih,
                   const float*  __restrict__ Whh,
                   const float*  __restrict__ bih,
                   const float*  __restrict__ bhh,
                   float4* __restrict__ out4,
                   float4* __restrict__ hout4,
                   int T, int npairs)
{
    int p = blockIdx.x * blockDim.x + threadIdx.x;
    if (p >= npairs) return;

    // 2x2 weights (row-major). z = x @ W^T  ->  z0 = W[0][0]*x0 + W[0][1]*x1
    const float a00 = Wih[0], a01 = Wih[1], a10 = Wih[2], a11 = Wih[3];
    const float w00 = Whh[0], w01 = Whh[1], w10 = Whh[2], w11 = Whh[3];
    const float b0 = bih[0] + bhh[0];
    const float b1 = bih[1] + bhh[1];

    float4 hv = h04[p];
    float hA0 = hv.x, hA1 = hv.y;   // batch element A
    float hB0 = hv.z, hB1 = hv.w;   // batch element B

    float4 xv = __ldcs(&x4[p]);     // prefetched x_t

    #pragma unroll 2
    for (int t = 0; t < T; ++t) {
        float4 xn;
        if (t + 1 < T) xn = __ldcs(&x4[(size_t)(t + 1) * npairs + p]);

        // --- batch element A: x = (xv.x, xv.y) ---
        float zA0 = fmaf(a00, xv.x, fmaf(a01, xv.y, fmaf(w00, hA0, fmaf(w01, hA1, b0))));
        float zA1 = fmaf(a10, xv.x, fmaf(a11, xv.y, fmaf(w10, hA0, fmaf(w11, hA1, b1))));
        // --- batch element B: x = (xv.z, xv.w) ---
        float zB0 = fmaf(a00, xv.z, fmaf(a01, xv.w, fmaf(w00, hB0, fmaf(w01, hB1, b0))));
        float zB1 = fmaf(a10, xv.z, fmaf(a11, xv.w, fmaf(w10, hB0, fmaf(w11, hB1, b1))));

        hA0 = fast_tanh(zA0);
        hA1 = fast_tanh(zA1);
        hB0 = fast_tanh(zB0);
        hB1 = fast_tanh(zB1);

        float4 o;
        o.x = fast_sig10(hA0);
        o.y = fast_sig10(hA1);
        o.z = fast_sig10(hB0);
        o.w = fast_sig10(hB1);
        __stcs(&out4[(size_t)t * npairs + p], o);

        xv = xn;
    }

    float4 hf;
    hf.x = hA0; hf.y = hA1; hf.z = hB0; hf.w = hB1;
    hout4[p] = hf;
}

extern "C" void kernel_launch(void* const* d_in, const int* in_sizes, int n_in,
                              void* d_out, int out_size)
{
    const float* x   = (const float*)d_in[0];   // (T, B, 2)
    const float* h0  = (const float*)d_in[1];   // (1, B, 2)
    const float* Wih = (const float*)d_in[2];   // (2, 2)
    const float* Whh = (const float*)d_in[3];   // (2, 2)
    const float* bih = (const float*)d_in[4];   // (2,)
    const float* bhh = (const float*)d_in[5];   // (2,)

    const int BH = in_sizes[1];                 // B * H = B * 2
    const int B  = BH / 2;
    const int T  = in_sizes[0] / BH;            // (T*B*2) / (B*2)

    float* out = (float*)d_out;                 // first T*B*2 elems: out
    float* hout = out + ((size_t)out_size - (size_t)BH);  // last B*2 elems: hidden

    const int npairs = B / 2;                   // float4 granularity (2 batch elems)
    const int threads = 256;
    const int blocks = (npairs + threads - 1) / threads;

    rnn_sigmoid_kernel<<<blocks, threads>>>(
        (const float4*)x, (const float4*)h0,
        Wih, Whh, bih, bhh,
        (float4*)out, (float4*)hout,
        T, npairs);
}